// round 17
// baseline (speedup 1.0000x reference)
#include <cuda_runtime.h>
#include <cstdint>

// Problem constants
#define BATCH 64
#define HDIM 56
#define WDIM 56
#define CDIM 256
#define ROUTES 4
#define CONV_OUT 64
#define ROUTE_W 64            // C / ROUTES
#define ROWG 14               // groups per image: 4 rows each
#define NSTAT 9
#define BN_EPS 1e-3f

#define G_F4_PER_B (HDIM * WDIM * ROUTE_W / 4)    // 12544

// Scratch (device globals — no allocation allowed)
__device__ float4 g_acc[BATCH * ROWG];    // per-(batch,group) logit contribution
__device__ float4 g_bias4;                // batch-independent bias over routes
__device__ float  g_W[9 * CDIM * ROUTES]; // folded conv@fc weights / 784

// float4 helpers (component-wise over the 4 routes)
__device__ __forceinline__ float4 f4add(float4 a, float4 b) {
    return make_float4(a.x + b.x, a.y + b.y, a.z + b.z, a.w + b.w);
}
__device__ __forceinline__ float4 f4fma(float s, float4 a, float4 acc) {
    return make_float4(fmaf(s, a.x, acc.x), fmaf(s, a.y, acc.y),
                       fmaf(s, a.z, acc.z), fmaf(s, a.w, acc.w));
}
__device__ __forceinline__ float4 f4scale(float s, float4 a) {
    return make_float4(s * a.x, s * a.y, s * a.z, s * a.w);
}

// ---------------------------------------------------------------------------
// L0: fold conv_w [3,3,256,64] with fc_w [64,4]:
//   g_W[k][ci][r] = (1/784) * sum_co conv_w[k][ci][co] * fc_w[co][r]
// ---------------------------------------------------------------------------
__global__ __launch_bounds__(CDIM) void k_weff(const float* __restrict__ conv_w,
                                               const float* __restrict__ fc_w)
{
    __shared__ float sf[CONV_OUT * ROUTES];
    const int k  = blockIdx.x;
    const int ci = threadIdx.x;
    sf[ci] = fc_w[ci];
    __syncthreads();

    const float* cw = conv_w + ((size_t)k * CDIM + ci) * CONV_OUT;
    float a0 = 0.f, a1 = 0.f, a2 = 0.f, a3 = 0.f;
    #pragma unroll 16
    for (int co = 0; co < CONV_OUT; ++co) {
        float wv = cw[co];
        a0 += wv * sf[co * 4 + 0];
        a1 += wv * sf[co * 4 + 1];
        a2 += wv * sf[co * 4 + 2];
        a3 += wv * sf[co * 4 + 3];
    }
    const float inv = 1.0f / 784.0f;
    float* o = g_W + ((size_t)k * CDIM + ci) * ROUTES;
    o[0] = a0 * inv; o[1] = a1 * inv; o[2] = a2 * inv; o[3] = a3 * inv;
}

// ---------------------------------------------------------------------------
// L1: sufficient statistics contracted in-block to a float4 logit contribution
// per (batch, rowgroup) [R7-verified math], plus one bias block.
// grid (14, 65): y<64 -> stats for (batch=y, group=x); y==64, x==0 -> bias.
// stats j: 0=EE 1=EO 2=OE 3=OO 4=R0E 5=R0O 6=C0E 7=C0O 8=P00
// ---------------------------------------------------------------------------
__global__ __launch_bounds__(256, 4) void k_stats(const float* __restrict__ in,
                                                  const float* __restrict__ gamma,
                                                  const float* __restrict__ beta,
                                                  const float* __restrict__ mmean,
                                                  const float* __restrict__ mvar,
                                                  const float* __restrict__ conv_b,
                                                  const float* __restrict__ fc_w,
                                                  const float* __restrict__ fc_b)
{
    const int tid = threadIdx.x;
    float4 Z = {0.f, 0.f, 0.f, 0.f};

    if (blockIdx.y == BATCH) {
        // ---- bias block (R7-verified): g_bias4 = sum_ci offs*nsum + conv_b@fc + fc_b
        if (blockIdx.x != 0) return;
        const int ci = tid;
        const float4* W4 = (const float4*)g_W;
        float4 W0 = W4[0 * CDIM + ci], W1 = W4[1 * CDIM + ci], W2 = W4[2 * CDIM + ci];
        float4 W3 = W4[3 * CDIM + ci], W4v = W4[4 * CDIM + ci], W5 = W4[5 * CDIM + ci];
        float4 W6 = W4[6 * CDIM + ci], W7 = W4[7 * CDIM + ci], W8 = W4[8 * CDIM + ci];

        float4 s784 = f4add(f4add(W0, W1), f4add(W3, W4v));
        float4 s756 = f4add(f4add(W2, W5), f4add(W6, W7));
        float4 nsum = f4fma(784.f, s784, f4fma(756.f, s756, f4scale(729.f, W8)));

        float sc = rsqrtf(mvar[ci] + BN_EPS) * gamma[ci];
        float of = beta[ci] - mmean[ci] * sc;
        float4 part = f4scale(of, nsum);
        if (ci < CONV_OUT)
            part = f4fma(conv_b[ci], ((const float4*)fc_w)[ci], part);

        #pragma unroll
        for (int o = 16; o > 0; o >>= 1) {
            part.x += __shfl_xor_sync(0xFFFFFFFFu, part.x, o);
            part.y += __shfl_xor_sync(0xFFFFFFFFu, part.y, o);
            part.z += __shfl_xor_sync(0xFFFFFFFFu, part.z, o);
            part.w += __shfl_xor_sync(0xFFFFFFFFu, part.w, o);
        }
        __shared__ float4 bred[8];
        if ((ci & 31) == 0) bred[ci >> 5] = part;
        __syncthreads();
        if (ci == 0) {
            float4 bsum = Z;
            #pragma unroll
            for (int w = 0; w < 8; ++w) bsum = f4add(bsum, bred[w]);
            bsum.x += fc_b[0]; bsum.y += fc_b[1]; bsum.z += fc_b[2]; bsum.w += fc_b[3];
            g_bias4 = bsum;
        }
        return;
    }

    const int b  = blockIdx.y;
    const int g  = blockIdx.x;            // 0..13
    const int c4 = tid & 63;
    const int s  = tid >> 6;              // row within group, 0..3

    const int h = g * 4 + s;
    const float4* row = (const float4*)(in
        + (((size_t)b * HDIM + h) * WDIM) * CDIM) + c4;

    float4 sE = Z, sO = Z, c0 = Z;

    #pragma unroll
    for (int i = 0; i < 7; ++i) {
        // 8 independent loads issued before any accumulation (MLP = 8)
        float4 v0 = row[(size_t)(8 * i + 0) * (CDIM/4)];
        float4 v1 = row[(size_t)(8 * i + 1) * (CDIM/4)];
        float4 v2 = row[(size_t)(8 * i + 2) * (CDIM/4)];
        float4 v3 = row[(size_t)(8 * i + 3) * (CDIM/4)];
        float4 v4 = row[(size_t)(8 * i + 4) * (CDIM/4)];
        float4 v5 = row[(size_t)(8 * i + 5) * (CDIM/4)];
        float4 v6 = row[(size_t)(8 * i + 6) * (CDIM/4)];
        float4 v7 = row[(size_t)(8 * i + 7) * (CDIM/4)];
        if (i == 0) c0 = v0;
        sE.x += (v0.x + v2.x) + (v4.x + v6.x);
        sE.y += (v0.y + v2.y) + (v4.y + v6.y);
        sE.z += (v0.z + v2.z) + (v4.z + v6.z);
        sE.w += (v0.w + v2.w) + (v4.w + v6.w);
        sO.x += (v1.x + v3.x) + (v5.x + v7.x);
        sO.y += (v1.y + v3.y) + (v5.y + v7.y);
        sO.z += (v1.z + v3.z) + (v5.z + v7.z);
        sO.w += (v1.w + v3.w) + (v5.w + v7.w);
    }

    __shared__ float4 sm[4][3][64];       // 12 KB
    sm[s][0][c4] = sE;
    sm[s][1][c4] = sO;
    sm[s][2][c4] = c0;
    __syncthreads();

    __shared__ float4 sred[2];
    float4 acc4 = Z;
    if (tid < 64) {
        float4 e0 = sm[0][0][tid], o0 = sm[0][1][tid], z0 = sm[0][2][tid]; // row g*4+0 (even)
        float4 e1 = sm[1][0][tid], o1 = sm[1][1][tid], z1 = sm[1][2][tid]; // row g*4+1 (odd)
        float4 e2 = sm[2][0][tid], o2 = sm[2][1][tid], z2 = sm[2][2][tid]; // row g*4+2 (even)
        float4 e3 = sm[3][0][tid], o3 = sm[3][1][tid], z3 = sm[3][2][tid]; // row g*4+3 (odd)

        float4 st[NSTAT];
        st[0] = f4add(e0, e2);            // EE
        st[1] = f4add(o0, o2);            // EO
        st[2] = f4add(e1, e3);            // OE
        st[3] = f4add(o1, o3);            // OO
        st[6] = f4add(z0, z2);            // C0E
        st[7] = f4add(z1, z3);            // C0O
        if (g == 0) { st[4] = e0; st[5] = o0; st[8] = z0; }
        else        { st[4] = Z;  st[5] = Z;  st[8] = Z;  }

        // BN scale for channels 4*tid..4*tid+3
        float4 gam = ((const float4*)gamma)[tid];
        float4 mv  = ((const float4*)mvar)[tid];
        float sc[4];
        sc[0] = rsqrtf(mv.x + BN_EPS) * gam.x;
        sc[1] = rsqrtf(mv.y + BN_EPS) * gam.y;
        sc[2] = rsqrtf(mv.z + BN_EPS) * gam.z;
        sc[3] = rsqrtf(mv.w + BN_EPS) * gam.w;

        const float4* W4 = (const float4*)g_W;   // [k][ci] -> float4 over routes
        #pragma unroll
        for (int cc = 0; cc < 4; ++cc) {
            const int ci = 4 * tid + cc;
            float4 W0 = W4[0 * CDIM + ci], W1 = W4[1 * CDIM + ci], W2 = W4[2 * CDIM + ci];
            float4 W3 = W4[3 * CDIM + ci], W4v = W4[4 * CDIM + ci], W5 = W4[5 * CDIM + ci];
            float4 W6 = W4[6 * CDIM + ci], W7 = W4[7 * CDIM + ci], W8 = W4[8 * CDIM + ci];

            float4 tEE  = f4add(f4add(W0, W2), f4add(W6, W8));
            float4 tEO  = f4add(W1, W7);
            float4 tOE  = f4add(W3, W5);
            float4 tR0E = f4add(W6, W8);
            float4 tC0E = f4add(W2, W8);

            float4 d = Z;
            d = f4fma( ((const float*)&st[0])[cc], tEE,  d);
            d = f4fma( ((const float*)&st[1])[cc], tEO,  d);
            d = f4fma( ((const float*)&st[2])[cc], tOE,  d);
            d = f4fma( ((const float*)&st[3])[cc], W4v,  d);
            d = f4fma(-((const float*)&st[4])[cc], tR0E, d);
            d = f4fma(-((const float*)&st[5])[cc], W7,   d);
            d = f4fma(-((const float*)&st[6])[cc], tC0E, d);
            d = f4fma(-((const float*)&st[7])[cc], W5,   d);
            d = f4fma( ((const float*)&st[8])[cc], W8,   d);
            acc4 = f4fma(sc[cc], d, acc4);
        }

        // warp reduce (2 full warps among tid<64)
        #pragma unroll
        for (int o = 16; o > 0; o >>= 1) {
            acc4.x += __shfl_xor_sync(0xFFFFFFFFu, acc4.x, o);
            acc4.y += __shfl_xor_sync(0xFFFFFFFFu, acc4.y, o);
            acc4.z += __shfl_xor_sync(0xFFFFFFFFu, acc4.z, o);
            acc4.w += __shfl_xor_sync(0xFFFFFFFFu, acc4.w, o);
        }
        if ((tid & 31) == 0) sred[tid >> 5] = acc4;
    }
    __syncthreads();
    if (tid == 0)
        g_acc[b * ROWG + g] = f4add(sred[0], sred[1]);
}

// ---------------------------------------------------------------------------
// L2: gather with inline route derivation. Each block sums the 14 group
// contributions + bias (fixed order -> deterministic), argmaxes, then copies
// the selected 64-channel slab (4 float4/thread). Block bx==0 also writes
// routing_x. Reverse scheduled so the input tail (L2-resident) goes first.
// grid (13, 64), 256 threads.
// ---------------------------------------------------------------------------
__global__ __launch_bounds__(256) void k_gather(const float* __restrict__ in,
                                                float* __restrict__ out,
                                                float* __restrict__ out_routing)
{
    const int b = (BATCH - 1) - blockIdx.y;
    const int bx = (gridDim.x - 1) - blockIdx.x;
    const int tid = threadIdx.x;

    __shared__ int route_s;
    if (tid == 0) {
        float4 v = g_bias4;
        #pragma unroll
        for (int g = 0; g < ROWG; ++g)
            v = f4add(v, g_acc[b * ROWG + g]);
        int best = 0; float bv = v.x;
        if (v.y > bv) { bv = v.y; best = 1; }
        if (v.z > bv) { bv = v.z; best = 2; }
        if (v.w > bv) { bv = v.w; best = 3; }
        route_s = best;
        if (bx == 0)
            ((float4*)out_routing)[b] = v;
    }
    __syncthreads();
    const int route = route_s;

    const float4* src4 = (const float4*)in + (size_t)b * (HDIM * WDIM) * (CDIM / 4)
                       + route * (ROUTE_W / 4);
    float4* dst4 = (float4*)out + (size_t)b * G_F4_PER_B;

    #pragma unroll
    for (int m = 0; m < 4; ++m) {
        const int t = bx * 1024 + m * 256 + tid;
        if (t < G_F4_PER_B) {
            const int pixel = t >> 4;
            const int q = t & 15;
            dst4[t] = src4[(size_t)pixel * (CDIM / 4) + q];
        }
    }
}

// ---------------------------------------------------------------------------
extern "C" void kernel_launch(void* const* d_in, const int* in_sizes, int n_in,
                              void* d_out, int out_size)
{
    const float* inputs  = (const float*)d_in[0];
    const float* gamma   = (const float*)d_in[1];
    const float* beta    = (const float*)d_in[2];
    const float* mmean   = (const float*)d_in[3];
    const float* mvar    = (const float*)d_in[4];
    const float* conv_w  = (const float*)d_in[5];
    const float* conv_b  = (const float*)d_in[6];
    const float* fc_w    = (const float*)d_in[7];
    const float* fc_b    = (const float*)d_in[8];

    float* out = (float*)d_out;
    // output layout: x [64,56,56,64] then routing_x [64,4]
    float* out_routing = out + ((size_t)out_size - BATCH * ROUTES);

    k_weff<<<9, CDIM>>>(conv_w, fc_w);
    k_stats<<<dim3(ROWG, BATCH + 1), 256>>>(inputs, gamma, beta, mmean, mvar,
                                            conv_b, fc_w, fc_b);
    k_gather<<<dim3((G_F4_PER_B + 1023) / 1024, BATCH), 256>>>(inputs, out, out_routing);
}